// round 13
// baseline (speedup 1.0000x reference)
#include <cuda_runtime.h>
#include <cuda_bf16.h>
#include <cstdint>

// ---------------------------------------------------------------------------
// TopKFrozenEmbeddings  (round 11: int8 IMMA screen GEMM + warp-per-row reduce)
//   GEMM is mma-dispatch-bound -> m16n8k32.s8 does 2x MACs per instruction.
//   Exactness: screen only picks top-24 candidates + moments; refine re-scores
//   candidates in exact fp32, so final top-10 matches reference given
//   containment (>10 sigma margin vs int8 logit noise).
// ---------------------------------------------------------------------------

#define N_TOK 4096
#define H     768
#define HR    192
#define VOC   50257
#define VP    50432            // 197*256 padded vocab
#define NCN   394              // 128-col chunks
#define KTOP  10
#define TOPC  24
#define NEG_INF (-3.402823466e38f)

#define QSCALE 640.0f          // 1/delta
#define QD2    2.44140625e-6f  // delta^2 = (1/640)^2

// ------------------------- device scratch ----------------------------------
__device__ float  g_xred[(size_t)N_TOK * HR];
__device__ float  g_ered[(size_t)VP * HR];
__device__ char   g_aq8[(size_t)N_TOK * HR];
__device__ char   g_bq8[(size_t)VP * HR];
__device__ float2 g_s12[(size_t)N_TOK * NCN];
__device__ float2 g_cv [(size_t)N_TOK * NCN];
__device__ int2   g_ci [(size_t)N_TOK * NCN];
__device__ int    g_candi[N_TOK * TOPC];
__device__ float  g_topv[N_TOK * KTOP];
__device__ int    g_topi[N_TOK * KTOP];
__device__ float  g_sumexp[N_TOK];

struct Part { float s1, s2, v1, v2; int i1, i2; };

// ------------------------- asm helpers -------------------------------------
__device__ __forceinline__ uint32_t smem_u32(const void* p) {
    uint32_t a;
    asm("{ .reg .u64 t; cvta.to.shared.u64 t, %1; cvt.u32.u64 %0, t; }"
        : "=r"(a) : "l"(p));
    return a;
}
#define CP_ASYNC16(s, g) \
    asm volatile("cp.async.cg.shared.global [%0], [%1], 16;" \
                 :: "r"(s), "l"(g) : "memory")
#define CP_COMMIT()  asm volatile("cp.async.commit_group;" ::: "memory")
#define CP_WAITG(n)  asm volatile("cp.async.wait_group %0;" :: "n"(n) : "memory")

#define LDSM_X4(r0, r1, r2, r3, addr) \
    asm volatile("ldmatrix.sync.aligned.m8n8.x4.shared.b16 {%0,%1,%2,%3}, [%4];" \
                 : "=r"(r0), "=r"(r1), "=r"(r2), "=r"(r3) : "r"(addr))

#define IMMA16832(d, a, b) \
    asm volatile("mma.sync.aligned.m16n8k32.row.col.s32.s8.s8.s32 " \
                 "{%0,%1,%2,%3}, {%4,%5,%6,%7}, {%8,%9}, {%0,%1,%2,%3};" \
                 : "+r"((d)[0]), "+r"((d)[1]), "+r"((d)[2]), "+r"((d)[3]) \
                 : "r"((a)[0]), "r"((a)[1]), "r"((a)[2]), "r"((a)[3]), \
                   "r"((b)[0]), "r"((b)[1]))

// ------------------------- pack kernels ------------------------------------
__device__ __forceinline__ char quant8(float v) {
    int q = __float2int_rn(v * QSCALE);
    q = max(-127, min(127, q));
    return (char)q;
}
__global__ void pack_x(const float* __restrict__ x) {
    int i = blockIdx.x * blockDim.x + threadIdx.x;
    if (i >= N_TOK * HR) return;
    int n = i / HR, k = i - n * HR;
    float v = 2.0f * x[(size_t)n * H + k * 4];      // sqrt(R)=2 exactly
    g_xred[i] = v;
    g_aq8[i] = quant8(v);
}
__global__ void pack_e(const float* __restrict__ e) {
    int i = blockIdx.x * blockDim.x + threadIdx.x;
    if (i >= VP * HR) return;
    int v = i / HR, k = i - v * HR;
    float val = (v < VOC) ? 2.0f * e[(size_t)v * H + k * 4] : 0.0f;
    g_ered[i] = val;
    g_bq8[i] = quant8(val);
}

// ------------------------- int8 IMMA GEMM + fused epilogue -----------------
// CTA tile 128(M) x 256(N), K=192 int8 in 2 chunks of 96B, 2 stages.
// 8 warps, warp tile 64x64. SMEM rows padded to 112B (conflict-free ldmatrix).
#define ROWB     112
#define STAGE_A  (128 * ROWB)           // 14336 B
#define STAGE_B  (256 * ROWB)           // 28672 B
#define STAGE_SZ (STAGE_A + STAGE_B)    // 43008 B
#define GEMM_SMEM (2 * STAGE_SZ)        // 86016 B

__global__ __launch_bounds__(256, 1) void gemm_imma() {
    extern __shared__ __align__(1024) char smem[];
    const uint32_t sb = smem_u32(smem);
    const int tid = threadIdx.x;
    const int bm = blockIdx.y * 128;
    const int bn = blockIdx.x * 256;

    auto load_chunk = [&](int kc, int stage) {
#pragma unroll
        for (int it = 0; it < 9; it++) {
            int s = tid + it * 256;              // 0..2303 16B transfers
            if (s < 768) {                        // A: 128 rows x 6 chunks
                int r = s / 6, c = s - r * 6;
                CP_ASYNC16(sb + stage * STAGE_SZ + r * ROWB + c * 16,
                           g_aq8 + (size_t)(bm + r) * HR + kc * 96 + c * 16);
            } else {                              // B: 256 rows x 6 chunks
                int t = s - 768; int r = t / 6, c = t - r * 6;
                CP_ASYNC16(sb + stage * STAGE_SZ + STAGE_A + r * ROWB + c * 16,
                           g_bq8 + (size_t)(bn + r) * HR + kc * 96 + c * 16);
            }
        }
        CP_COMMIT();
    };

    const int w = tid >> 5, lane = tid & 31;
    const int wm = (w >> 2) * 64;        // 2 M-warps
    const int wn = (w & 3) * 64;         // 4 N-warps
    // ldmatrix source rows/cols (x4 tile layout verified for s8 k32 frags)
    const int arow = (lane & 7) + ((lane >> 3) & 1) * 8;
    const int acol = (lane >> 4) * 16;
    const int brow = (lane & 7) + ((lane >> 4) << 3);
    const int bcol = ((lane >> 3) & 1) * 16;

    int acc[4][8][4];
#pragma unroll
    for (int mi = 0; mi < 4; mi++)
#pragma unroll
        for (int ni = 0; ni < 8; ni++)
#pragma unroll
            for (int q = 0; q < 4; q++) acc[mi][ni][q] = 0;

    auto compute_stage = [&](int stage) {
        const uint32_t sA = sb + stage * STAGE_SZ;
        const uint32_t sB = sA + STAGE_A;
#pragma unroll
        for (int ks = 0; ks < 3; ks++) {         // 3 x k32 per 96B chunk
            uint32_t a[4][4];
#pragma unroll
            for (int mi = 0; mi < 4; mi++) {
                int r = wm + mi * 16 + arow;
                LDSM_X4(a[mi][0], a[mi][1], a[mi][2], a[mi][3],
                        sA + r * ROWB + ks * 32 + acol);
            }
            uint32_t b[8][2];
#pragma unroll
            for (int p = 0; p < 4; p++) {
                int r = wn + p * 16 + brow;
                uint32_t r0, r1, r2, r3;
                LDSM_X4(r0, r1, r2, r3, sB + r * ROWB + ks * 32 + bcol);
                b[2 * p + 0][0] = r0; b[2 * p + 0][1] = r1;
                b[2 * p + 1][0] = r2; b[2 * p + 1][1] = r3;
            }
#pragma unroll
            for (int mi = 0; mi < 4; mi++)
#pragma unroll
                for (int ni = 0; ni < 8; ni++)
                    IMMA16832(acc[mi][ni], a[mi], b[ni]);
        }
    };

    // ---- pipeline: 2 chunks -> stages 0,1
    load_chunk(0, 0);
    load_chunk(1, 1);
    CP_WAITG(1); __syncthreads();
    compute_stage(0);
    CP_WAITG(0); __syncthreads();
    compute_stage(1);

    // ---- fused epilogue: per-row Σl, Σl², top-2 per 128-col chunk
    __syncthreads();
    Part* parts = (Part*)smem;           // [128 rows][4 n-warps]

#pragma unroll
    for (int mi = 0; mi < 4; mi++) {
#pragma unroll
        for (int h = 0; h < 2; h++) {
            float s1 = 0.0f, s2 = 0.0f;
            float v1 = NEG_INF, v2 = NEG_INF; int i1 = 0, i2 = 0;
#pragma unroll
            for (int ni = 0; ni < 8; ni++) {
#pragma unroll
                for (int j = 0; j < 2; j++) {
                    float v = (float)acc[mi][ni][h * 2 + j] * QD2;
                    int col = wn + ni * 8 + (lane & 3) * 2 + j;
                    s1 += v; s2 = fmaf(v, v, s2);
                    if (v > v1)      { v2 = v1; i2 = i1; v1 = v; i1 = col; }
                    else if (v > v2) { v2 = v;  i2 = col; }
                }
            }
#pragma unroll
            for (int d = 1; d <= 2; d <<= 1) {
                float o1 = __shfl_xor_sync(0xffffffffu, s1, d);
                float o2 = __shfl_xor_sync(0xffffffffu, s2, d);
                float w1 = __shfl_xor_sync(0xffffffffu, v1, d);
                float w2 = __shfl_xor_sync(0xffffffffu, v2, d);
                int   j1 = __shfl_xor_sync(0xffffffffu, i1, d);
                int   j2 = __shfl_xor_sync(0xffffffffu, i2, d);
                s1 += o1; s2 += o2;
                if (w1 > v1) {
                    float nv2; int ni2;
                    if (v1 >= w2) { nv2 = v1; ni2 = i1; }
                    else          { nv2 = w2; ni2 = j2; }
                    v1 = w1; i1 = j1; v2 = nv2; i2 = ni2;
                } else if (w1 > v2) {
                    v2 = w1; i2 = j1;
                }
            }
            if ((lane & 3) == 0) {
                int r = wm + mi * 16 + h * 8 + (lane >> 2);
                Part p; p.s1 = s1; p.s2 = s2; p.v1 = v1; p.v2 = v2;
                p.i1 = i1; p.i2 = i2;
                parts[r * 4 + (w & 3)] = p;
            }
        }
    }
    __syncthreads();

    // 256 threads: (row, chunk-half) pairs. chunk ch merges n-warps 2ch, 2ch+1
    {
        int r = tid >> 1, ch = tid & 1;
        float s1 = 0.0f, s2 = 0.0f;
        float v1 = NEG_INF, v2 = NEG_INF; int i1 = 0, i2 = 0;
#pragma unroll
        for (int q = 0; q < 2; q++) {
            Part p = parts[r * 4 + ch * 2 + q];
            s1 += p.s1; s2 += p.s2;
            if (p.v1 > v1) {
                float nv2; int ni2;
                if (v1 >= p.v2) { nv2 = v1;   ni2 = i1; }
                else            { nv2 = p.v2; ni2 = p.i2; }
                v1 = p.v1; i1 = p.i1; v2 = nv2; i2 = ni2;
            } else if (p.v1 > v2) {
                v2 = p.v1; i2 = p.i1;
            }
        }
        size_t o = (size_t)(bm + r) * NCN + blockIdx.x * 2 + ch;
        g_s12[o] = make_float2(s1, s2);
        g_cv[o]  = make_float2(v1, v2);
        g_ci[o]  = make_int2(bn + i1, bn + i2);
    }
}

// ------------------------- warp-per-row reduce: Σexp poly + top-24 ---------
// 788 candidates/row -> 25 per lane; 24 barrier-free argmax rounds.
__global__ __launch_bounds__(256) void reduce_rows() {
    const int row  = blockIdx.x * 8 + (threadIdx.x >> 5);
    const int lane = threadIdx.x & 31;

    // ---- moments: Σexp ≈ VOC + Σl + ½Σl²
    float s = 0.0f;
    for (int c = lane; c < NCN; c += 32) {
        float2 p = g_s12[(size_t)row * NCN + c];
        s += fmaf(0.5f, p.y, p.x);
    }
#pragma unroll
    for (int d = 16; d > 0; d >>= 1) s += __shfl_xor_sync(0xffffffffu, s, d);
    if (lane == 0) g_sumexp[row] = (float)VOC + s;

    // ---- candidates: 2 per chunk = 788, padded to 800 = 25 slots/lane
    float v[25]; int ix[25];
#pragma unroll
    for (int q = 0; q < 25; q++) {
        int slot = q * 32 + lane;
        int c = slot >> 1;
        if (c < NCN) {
            float2 cv = g_cv[(size_t)row * NCN + c];
            int2   ci = g_ci[(size_t)row * NCN + c];
            v[q]  = (slot & 1) ? cv.y : cv.x;
            ix[q] = (slot & 1) ? ci.y : ci.x;
        } else { v[q] = NEG_INF; ix[q] = 0x7fffffff; }
    }

    for (int r = 0; r < TOPC; r++) {
        float bv = v[0]; int bi = ix[0];
#pragma unroll
        for (int q = 1; q < 25; q++)
            if (v[q] > bv || (v[q] == bv && ix[q] < bi)) { bv = v[q]; bi = ix[q]; }
#pragma unroll
        for (int d = 16; d > 0; d >>= 1) {
            float ov = __shfl_xor_sync(0xffffffffu, bv, d);
            int   oi = __shfl_xor_sync(0xffffffffu, bi, d);
            if (ov > bv || (ov == bv && oi < bi)) { bv = ov; bi = oi; }
        }
        if (lane == 0) g_candi[row * TOPC + r] = bi;
#pragma unroll
        for (int q = 0; q < 25; q++)             // consume winner (idx unique)
            if (v[q] == bv && ix[q] == bi) v[q] = NEG_INF;
    }
}

// ------------------------- fp32 refine: exact reduced logits, top-10 -------
__global__ __launch_bounds__(256) void refine() {
    const int row = blockIdx.x;
    const int tid = threadIdx.x;
    const int w = tid >> 5, lane = tid & 31;
    __shared__ float xs[HR];
    __shared__ float cval[TOPC];
    __shared__ int   cidx[TOPC];

    for (int i = tid; i < HR; i += 256) xs[i] = g_xred[(size_t)row * HR + i];
    __syncthreads();

    for (int c = w; c < TOPC; c += 8) {
        int idx = g_candi[row * TOPC + c];
        if ((unsigned)idx >= (unsigned)VP) idx = 0;          // defensive clamp
        const float* er = g_ered + (size_t)idx * HR;
        float d = 0.0f;
#pragma unroll
        for (int h0 = 0; h0 < HR; h0 += 32) d = fmaf(xs[h0 + lane], er[h0 + lane], d);
#pragma unroll
        for (int st = 16; st > 0; st >>= 1) d += __shfl_xor_sync(0xffffffffu, d, st);
        if (lane == 0) { cval[c] = d; cidx[c] = idx; }
    }
    __syncthreads();

    if (tid == 0) {
        bool used[TOPC];
#pragma unroll
        for (int c = 0; c < TOPC; c++) used[c] = false;
#pragma unroll
        for (int r = 0; r < KTOP; r++) {
            float bv = NEG_INF; int bi = 0x7fffffff; int bp = 0;
#pragma unroll
            for (int c = 0; c < TOPC; c++) {
                if (used[c]) continue;
                if (cval[c] > bv || (cval[c] == bv && cidx[c] < bi)) {
                    bv = cval[c]; bi = cidx[c]; bp = c;
                }
            }
            used[bp] = true;
            g_topv[row * KTOP + r] = bv;
            g_topi[row * KTOP + r] = bi;
        }
    }
}

// ------------------------- exact full-H rescore + combine ------------------
__global__ __launch_bounds__(320) void rescore(const float* __restrict__ x,
                                               const float* __restrict__ emb,
                                               float* __restrict__ out) {
    const int row = blockIdx.x;
    const int tid = threadIdx.x;
    const int w = tid >> 5, lane = tid & 31;
    __shared__ float s_el[KTOP];

    if (w < KTOP) {
        int idx = g_topi[row * KTOP + w];
        if ((unsigned)idx >= (unsigned)VOC) idx = 0;         // defensive clamp
        const float* xr = x + (size_t)row * H;
        const float* er = emb + (size_t)idx * H;
        float d = 0.0f;
        for (int h = lane; h < H; h += 32) d = fmaf(xr[h], er[h], d);
#pragma unroll
        for (int st = 16; st > 0; st >>= 1) d += __shfl_xor_sync(0xffffffffu, d, st);
        if (lane == 0) s_el[w] = d;
    }
    __syncthreads();

    if (tid == 0) {
        float Z = g_sumexp[row];
        float es[KTOP]; float zs = 0.0f;
#pragma unroll
        for (int k = 0; k < KTOP; k++) { es[k] = __expf(s_el[k]); zs += es[k]; }
        float best = NEG_INF;
#pragma unroll
        for (int k = 0; k < KTOP; k++) {
            float sc = 0.5f * (es[k] / zs + __expf(g_topv[row * KTOP + k]) / Z);
            best = fmaxf(best, sc);
        }
        out[row] = best;
    }
}

// ------------------------- launch ------------------------------------------
extern "C" void kernel_launch(void* const* d_in, const int* in_sizes, int n_in,
                              void* d_out, int out_size) {
    const float* x   = (const float*)d_in[0];
    const float* emb = (const float*)d_in[1];
    if (n_in >= 2 && in_sizes[0] != N_TOK * H) {
        const float* t = x; x = emb; emb = t;
    }
    float* out = (float*)d_out;

    static bool attr_done = false;
    if (!attr_done) {
        cudaFuncSetAttribute(gemm_imma, cudaFuncAttributeMaxDynamicSharedMemorySize,
                             GEMM_SMEM);
        attr_done = true;
    }

    pack_x<<<(N_TOK * HR + 255) / 256, 256>>>(x);
    pack_e<<<(VP * HR + 255) / 256, 256>>>(emb);

    dim3 ggrid(VP / 256, N_TOK / 128);      // (197, 32)
    gemm_imma<<<ggrid, 256, GEMM_SMEM>>>();

    reduce_rows<<<N_TOK / 8, 256>>>();
    refine<<<N_TOK, 256>>>();
    rescore<<<N_TOK, 320>>>(x, emb, out);
}

// round 14
// speedup vs baseline: 1.5225x; 1.5225x over previous
#include <cuda_runtime.h>
#include <cuda_bf16.h>
#include <cstdint>

// ---------------------------------------------------------------------------
// TopKFrozenEmbeddings  (round 13: revert to bf16 HMMA GEMM [R11-proven],
//   keep warp-per-row reduce [R13-proven], merge refine+rescore -> finalize)
//   Falsified: legacy int8 IMMA is NOT fast on sm_103 (~2x slower than HMMA).
// ---------------------------------------------------------------------------

#define N_TOK 4096
#define H     768
#define HR    192
#define VOC   50257
#define VP    50432            // 197*256 padded vocab
#define NCN   394              // 128-col chunks
#define KTOP  10
#define TOPC  24
#define NEG_INF (-3.402823466e38f)

// ------------------------- device scratch ----------------------------------
__device__ float         g_xred[(size_t)N_TOK * HR];
__device__ float         g_ered[(size_t)VP * HR];
__device__ __nv_bfloat16 g_abf[(size_t)N_TOK * HR];
__device__ __nv_bfloat16 g_bbf[(size_t)VP * HR];
__device__ float2 g_s12[(size_t)N_TOK * NCN];
__device__ float2 g_cv [(size_t)N_TOK * NCN];
__device__ int2   g_ci [(size_t)N_TOK * NCN];
__device__ int    g_candi[N_TOK * TOPC];
__device__ float  g_sumexp[N_TOK];

struct Part { float s1, s2, v1, v2; int i1, i2; };

// ------------------------- asm helpers -------------------------------------
__device__ __forceinline__ uint32_t smem_u32(const void* p) {
    uint32_t a;
    asm("{ .reg .u64 t; cvta.to.shared.u64 t, %1; cvt.u32.u64 %0, t; }"
        : "=r"(a) : "l"(p));
    return a;
}
#define CP_ASYNC16(s, g) \
    asm volatile("cp.async.cg.shared.global [%0], [%1], 16;" \
                 :: "r"(s), "l"(g) : "memory")
#define CP_COMMIT()  asm volatile("cp.async.commit_group;" ::: "memory")
#define CP_WAITG(n)  asm volatile("cp.async.wait_group %0;" :: "n"(n) : "memory")

#define LDSM_X4(r0, r1, r2, r3, addr) \
    asm volatile("ldmatrix.sync.aligned.m8n8.x4.shared.b16 {%0,%1,%2,%3}, [%4];" \
                 : "=r"(r0), "=r"(r1), "=r"(r2), "=r"(r3) : "r"(addr))

#define MMA16816(d, a, b) \
    asm volatile("mma.sync.aligned.m16n8k16.row.col.f32.bf16.bf16.f32 " \
                 "{%0,%1,%2,%3}, {%4,%5,%6,%7}, {%8,%9}, {%0,%1,%2,%3};" \
                 : "+f"((d)[0]), "+f"((d)[1]), "+f"((d)[2]), "+f"((d)[3]) \
                 : "r"((a)[0]), "r"((a)[1]), "r"((a)[2]), "r"((a)[3]), \
                   "r"((b)[0]), "r"((b)[1]))

// ------------------------- pack kernels ------------------------------------
__global__ void pack_x(const float* __restrict__ x) {
    int i = blockIdx.x * blockDim.x + threadIdx.x;
    if (i >= N_TOK * HR) return;
    int n = i / HR, k = i - n * HR;
    float v = 2.0f * x[(size_t)n * H + k * 4];      // sqrt(R)=2 exactly
    g_xred[i] = v;
    g_abf[i] = __float2bfloat16(v);
}
__global__ void pack_e(const float* __restrict__ e) {
    int i = blockIdx.x * blockDim.x + threadIdx.x;
    if (i >= VP * HR) return;
    int v = i / HR, k = i - v * HR;
    float val = (v < VOC) ? 2.0f * e[(size_t)v * H + k * 4] : 0.0f;
    g_ered[i] = val;
    g_bbf[i] = __float2bfloat16(val);
}

// ------------------------- pipelined bf16 mma GEMM + fused epilogue --------
// CTA tile 128(M) x 256(N), K=192 in 3 chunks of 64 (128B rows), 2 stages.
// 8 warps, warp tile 64x64. Chunks 0,1,2 -> stages 0,1,0.
#define STAGE_A  (128 * 128)            // 16384 B
#define STAGE_B  (256 * 128)            // 32768 B
#define STAGE_SZ (STAGE_A + STAGE_B)    // 49152 B
#define GEMM_SMEM (2 * STAGE_SZ)        // 98304 B

__global__ __launch_bounds__(256, 1) void gemm_mma() {
    extern __shared__ __align__(1024) char smem[];
    const uint32_t sb = smem_u32(smem);
    const int tid = threadIdx.x;
    const int bm = blockIdx.y * 128;
    const int bn = blockIdx.x * 256;

    const char* gA = (const char*)g_abf + (size_t)bm * 384;
    const char* gB = (const char*)g_bbf + (size_t)bn * 384;

    auto load_chunk = [&](int kc, int stage) {
#pragma unroll
        for (int it = 0; it < 12; it++) {
            int s = tid + it * 256;              // 0..3071 16B transfers
            if (s < 1024) {
                int r = s >> 3, c = s & 7;
                CP_ASYNC16(sb + stage * STAGE_SZ + r * 128 + ((c ^ (r & 7)) << 4),
                           gA + (size_t)r * 384 + kc * 128 + c * 16);
            } else {
                int t = s - 1024; int r = t >> 3, c = t & 7;
                CP_ASYNC16(sb + stage * STAGE_SZ + STAGE_A + r * 128 +
                               ((c ^ (r & 7)) << 4),
                           gB + (size_t)r * 384 + kc * 128 + c * 16);
            }
        }
        CP_COMMIT();
    };

    const int w = tid >> 5, lane = tid & 31;
    const int wm = (w >> 2) * 64;        // 2 M-warps
    const int wn = (w & 3) * 64;         // 4 N-warps
    const int arow0 = wm + (lane & 15);
    const int aco   = (lane >> 4);
    const int brow0 = wn + (lane & 7) + ((lane >> 4) << 3);
    const int bco   = (lane >> 3) & 1;

    float acc[4][8][4];
#pragma unroll
    for (int mi = 0; mi < 4; mi++)
#pragma unroll
        for (int ni = 0; ni < 8; ni++)
#pragma unroll
            for (int q = 0; q < 4; q++) acc[mi][ni][q] = 0.0f;

    auto compute_stage = [&](int stage) {        // arg is a STAGE index (0/1)
        const uint32_t sA = sb + stage * STAGE_SZ;
        const uint32_t sB = sA + STAGE_A;
#pragma unroll
        for (int k16 = 0; k16 < 4; k16++) {
            uint32_t a[4][4];
#pragma unroll
            for (int mi = 0; mi < 4; mi++) {
                int r = arow0 + mi * 16;
                int c = (k16 * 2 + aco) ^ (r & 7);
                LDSM_X4(a[mi][0], a[mi][1], a[mi][2], a[mi][3],
                        sA + r * 128 + (c << 4));
            }
            uint32_t b[8][2];
#pragma unroll
            for (int p = 0; p < 4; p++) {
                int r = brow0 + p * 16;
                int c = (k16 * 2 + bco) ^ (r & 7);
                uint32_t r0, r1, r2, r3;
                LDSM_X4(r0, r1, r2, r3, sB + r * 128 + (c << 4));
                b[2 * p + 0][0] = r0; b[2 * p + 0][1] = r1;
                b[2 * p + 1][0] = r2; b[2 * p + 1][1] = r3;
            }
#pragma unroll
            for (int mi = 0; mi < 4; mi++)
#pragma unroll
                for (int ni = 0; ni < 8; ni++)
                    MMA16816(acc[mi][ni], a[mi], b[ni]);
        }
    };

    // ---- pipeline: chunks 0,1,2 -> stages 0,1,0
    load_chunk(0, 0);
    load_chunk(1, 1);
    CP_WAITG(1); __syncthreads();        // chunk 0 (stage 0) ready
    compute_stage(0);
    __syncthreads();                      // stage 0 free for chunk 2
    load_chunk(2, 0);
    CP_WAITG(1); __syncthreads();        // chunk 1 (stage 1) ready
    compute_stage(1);
    CP_WAITG(0); __syncthreads();        // chunk 2 (stage 0) ready
    compute_stage(0);

    // ---- fused epilogue: per-row Σl, Σl², top-2 per 128-col chunk
    __syncthreads();
    Part* parts = (Part*)smem;           // [128 rows][4 n-warps]

#pragma unroll
    for (int mi = 0; mi < 4; mi++) {
#pragma unroll
        for (int h = 0; h < 2; h++) {
            float s1 = 0.0f, s2 = 0.0f;
            float v1 = NEG_INF, v2 = NEG_INF; int i1 = 0, i2 = 0;
#pragma unroll
            for (int ni = 0; ni < 8; ni++) {
#pragma unroll
                for (int j = 0; j < 2; j++) {
                    float v = acc[mi][ni][h * 2 + j];
                    int col = wn + ni * 8 + (lane & 3) * 2 + j;
                    s1 += v; s2 = fmaf(v, v, s2);
                    if (v > v1)      { v2 = v1; i2 = i1; v1 = v; i1 = col; }
                    else if (v > v2) { v2 = v;  i2 = col; }
                }
            }
#pragma unroll
            for (int d = 1; d <= 2; d <<= 1) {
                float o1 = __shfl_xor_sync(0xffffffffu, s1, d);
                float o2 = __shfl_xor_sync(0xffffffffu, s2, d);
                float w1 = __shfl_xor_sync(0xffffffffu, v1, d);
                float w2 = __shfl_xor_sync(0xffffffffu, v2, d);
                int   j1 = __shfl_xor_sync(0xffffffffu, i1, d);
                int   j2 = __shfl_xor_sync(0xffffffffu, i2, d);
                s1 += o1; s2 += o2;
                if (w1 > v1) {
                    float nv2; int ni2;
                    if (v1 >= w2) { nv2 = v1; ni2 = i1; }
                    else          { nv2 = w2; ni2 = j2; }
                    v1 = w1; i1 = j1; v2 = nv2; i2 = ni2;
                } else if (w1 > v2) {
                    v2 = w1; i2 = j1;
                }
            }
            if ((lane & 3) == 0) {
                int r = wm + mi * 16 + h * 8 + (lane >> 2);
                Part p; p.s1 = s1; p.s2 = s2; p.v1 = v1; p.v2 = v2;
                p.i1 = i1; p.i2 = i2;
                parts[r * 4 + (w & 3)] = p;
            }
        }
    }
    __syncthreads();

    // 256 threads: (row, chunk-half) pairs. chunk ch merges n-warps 2ch, 2ch+1
    {
        int r = tid >> 1, ch = tid & 1;
        float s1 = 0.0f, s2 = 0.0f;
        float v1 = NEG_INF, v2 = NEG_INF; int i1 = 0, i2 = 0;
#pragma unroll
        for (int q = 0; q < 2; q++) {
            Part p = parts[r * 4 + ch * 2 + q];
            s1 += p.s1; s2 += p.s2;
            if (p.v1 > v1) {
                float nv2; int ni2;
                if (v1 >= p.v2) { nv2 = v1;   ni2 = i1; }
                else            { nv2 = p.v2; ni2 = p.i2; }
                v1 = p.v1; i1 = p.i1; v2 = nv2; i2 = ni2;
            } else if (p.v1 > v2) {
                v2 = p.v1; i2 = p.i1;
            }
        }
        size_t o = (size_t)(bm + r) * NCN + blockIdx.x * 2 + ch;
        g_s12[o] = make_float2(s1, s2);
        g_cv[o]  = make_float2(v1, v2);
        g_ci[o]  = make_int2(bn + i1, bn + i2);
    }
}

// ------------------------- warp-per-row reduce: Σexp poly + top-24 ---------
// 788 candidates/row -> 25 per lane; 24 barrier-free argmax rounds.
__global__ __launch_bounds__(256) void reduce_rows() {
    const int row  = blockIdx.x * 8 + (threadIdx.x >> 5);
    const int lane = threadIdx.x & 31;

    // ---- moments: Σexp ≈ VOC + Σl + ½Σl² (pad cols are exactly 0)
    float s = 0.0f;
    for (int c = lane; c < NCN; c += 32) {
        float2 p = g_s12[(size_t)row * NCN + c];
        s += fmaf(0.5f, p.y, p.x);
    }
#pragma unroll
    for (int d = 16; d > 0; d >>= 1) s += __shfl_xor_sync(0xffffffffu, s, d);
    if (lane == 0) g_sumexp[row] = (float)VOC + s;

    // ---- candidates: 2 per chunk = 788, padded to 800 = 25 slots/lane
    float v[25]; int ix[25];
#pragma unroll
    for (int q = 0; q < 25; q++) {
        int slot = q * 32 + lane;
        int c = slot >> 1;
        if (c < NCN) {
            float2 cv = g_cv[(size_t)row * NCN + c];
            int2   ci = g_ci[(size_t)row * NCN + c];
            v[q]  = (slot & 1) ? cv.y : cv.x;
            ix[q] = (slot & 1) ? ci.y : ci.x;
        } else { v[q] = NEG_INF; ix[q] = 0x7fffffff; }
    }

    for (int r = 0; r < TOPC; r++) {
        float bv = v[0]; int bi = ix[0];
#pragma unroll
        for (int q = 1; q < 25; q++)
            if (v[q] > bv || (v[q] == bv && ix[q] < bi)) { bv = v[q]; bi = ix[q]; }
#pragma unroll
        for (int d = 16; d > 0; d >>= 1) {
            float ov = __shfl_xor_sync(0xffffffffu, bv, d);
            int   oi = __shfl_xor_sync(0xffffffffu, bi, d);
            if (ov > bv || (ov == bv && oi < bi)) { bv = ov; bi = oi; }
        }
        if (lane == 0) g_candi[row * TOPC + r] = bi;
#pragma unroll
        for (int q = 0; q < 25; q++)             // consume winner (idx unique)
            if (v[q] == bv && ix[q] == bi) v[q] = NEG_INF;
    }
}

// ------------------------- finalize: refine top-24 -> top-10 -> rescore ----
// One block (320 thr) per row. Phase A: exact fp32 reduced-dim dots for the
// 24 candidates. Phase B: exact top-10 selection (reference tie-break).
// Phase C: full-H fp32 rescore of the 10. Phase D: combine + max.
__global__ __launch_bounds__(320) void finalize(const float* __restrict__ x,
                                                const float* __restrict__ emb,
                                                float* __restrict__ out) {
    const int row = blockIdx.x;
    const int tid = threadIdx.x;
    const int w = tid >> 5, lane = tid & 31;

    __shared__ float xs[HR];
    __shared__ float cval[TOPC];
    __shared__ int   cidx[TOPC];
    __shared__ float tv[KTOP];
    __shared__ int   ti[KTOP];
    __shared__ float s_el[KTOP];

    for (int i = tid; i < HR; i += 320) xs[i] = g_xred[(size_t)row * HR + i];
    __syncthreads();

    // ---- Phase A: 10 warps cover 24 candidates (w, w+10, w+20)
    for (int c = w; c < TOPC; c += 10) {
        int idx = g_candi[row * TOPC + c];
        if ((unsigned)idx >= (unsigned)VP) idx = 0;          // defensive clamp
        const float* er = g_ered + (size_t)idx * HR;
        float d = 0.0f;
#pragma unroll
        for (int h0 = 0; h0 < HR; h0 += 32) d = fmaf(xs[h0 + lane], er[h0 + lane], d);
#pragma unroll
        for (int st = 16; st > 0; st >>= 1) d += __shfl_xor_sync(0xffffffffu, d, st);
        if (lane == 0) { cval[c] = d; cidx[c] = idx; }
    }
    __syncthreads();

    // ---- Phase B: exact top-10 (serial, tiny)
    if (tid == 0) {
        bool used[TOPC];
#pragma unroll
        for (int c = 0; c < TOPC; c++) used[c] = false;
#pragma unroll
        for (int r = 0; r < KTOP; r++) {
            float bv = NEG_INF; int bi = 0x7fffffff; int bp = 0;
#pragma unroll
            for (int c = 0; c < TOPC; c++) {
                if (used[c]) continue;
                if (cval[c] > bv || (cval[c] == bv && cidx[c] < bi)) {
                    bv = cval[c]; bi = cidx[c]; bp = c;
                }
            }
            used[bp] = true;
            tv[r] = bv; ti[r] = bi;
        }
    }
    __syncthreads();

    // ---- Phase C: full-H rescore, warp w -> candidate w
    if (w < KTOP) {
        int idx = ti[w];
        if ((unsigned)idx >= (unsigned)VOC) idx = 0;         // defensive clamp
        const float* xr = x + (size_t)row * H;
        const float* er = emb + (size_t)idx * H;
        float d = 0.0f;
        for (int h = lane; h < H; h += 32) d = fmaf(xr[h], er[h], d);
#pragma unroll
        for (int st = 16; st > 0; st >>= 1) d += __shfl_xor_sync(0xffffffffu, d, st);
        if (lane == 0) s_el[w] = d;
    }
    __syncthreads();

    // ---- Phase D: combine
    if (tid == 0) {
        float Z = g_sumexp[row];
        float es[KTOP]; float zs = 0.0f;
#pragma unroll
        for (int k = 0; k < KTOP; k++) { es[k] = __expf(s_el[k]); zs += es[k]; }
        float best = NEG_INF;
#pragma unroll
        for (int k = 0; k < KTOP; k++) {
            float sc = 0.5f * (es[k] / zs + __expf(tv[k]) / Z);
            best = fmaxf(best, sc);
        }
        out[row] = best;
    }
}

// ------------------------- launch ------------------------------------------
extern "C" void kernel_launch(void* const* d_in, const int* in_sizes, int n_in,
                              void* d_out, int out_size) {
    const float* x   = (const float*)d_in[0];
    const float* emb = (const float*)d_in[1];
    if (n_in >= 2 && in_sizes[0] != N_TOK * H) {
        const float* t = x; x = emb; emb = t;
    }
    float* out = (float*)d_out;

    static bool attr_done = false;
    if (!attr_done) {
        cudaFuncSetAttribute(gemm_mma, cudaFuncAttributeMaxDynamicSharedMemorySize,
                             GEMM_SMEM);
        attr_done = true;
    }

    pack_x<<<(N_TOK * HR + 255) / 256, 256>>>(x);
    pack_e<<<(VP * HR + 255) / 256, 256>>>(emb);

    dim3 ggrid(VP / 256, N_TOK / 128);      // (197, 32)
    gemm_mma<<<ggrid, 256, GEMM_SMEM>>>();

    reduce_rows<<<N_TOK / 8, 256>>>();
    finalize<<<N_TOK, 320>>>(x, emb, out);
}

// round 15
// speedup vs baseline: 1.6375x; 1.0755x over previous
#include <cuda_runtime.h>
#include <cuda_bf16.h>
#include <cstdint>

// ---------------------------------------------------------------------------
// TopKFrozenEmbeddings  (round 15: 16-warp GEMM for 4 warps/SMSP latency
//   hiding; revert to split refine+rescore from the measured-512us run)
// ---------------------------------------------------------------------------

#define N_TOK 4096
#define H     768
#define HR    192
#define VOC   50257
#define VP    50432            // 197*256 padded vocab
#define NCN   394              // 128-col chunks
#define KTOP  10
#define TOPC  24
#define NEG_INF (-3.402823466e38f)

// ------------------------- device scratch ----------------------------------
__device__ float         g_xred[(size_t)N_TOK * HR];
__device__ float         g_ered[(size_t)VP * HR];
__device__ __nv_bfloat16 g_abf[(size_t)N_TOK * HR];
__device__ __nv_bfloat16 g_bbf[(size_t)VP * HR];
__device__ float2 g_s12[(size_t)N_TOK * NCN];
__device__ float2 g_cv [(size_t)N_TOK * NCN];
__device__ int2   g_ci [(size_t)N_TOK * NCN];
__device__ int    g_candi[N_TOK * TOPC];
__device__ float  g_topv[N_TOK * KTOP];
__device__ int    g_topi[N_TOK * KTOP];
__device__ float  g_sumexp[N_TOK];

struct Part { float s1, s2, v1, v2; int i1, i2; };

// ------------------------- asm helpers -------------------------------------
__device__ __forceinline__ uint32_t smem_u32(const void* p) {
    uint32_t a;
    asm("{ .reg .u64 t; cvta.to.shared.u64 t, %1; cvt.u32.u64 %0, t; }"
        : "=r"(a) : "l"(p));
    return a;
}
#define CP_ASYNC16(s, g) \
    asm volatile("cp.async.cg.shared.global [%0], [%1], 16;" \
                 :: "r"(s), "l"(g) : "memory")
#define CP_COMMIT()  asm volatile("cp.async.commit_group;" ::: "memory")
#define CP_WAITG(n)  asm volatile("cp.async.wait_group %0;" :: "n"(n) : "memory")

#define LDSM_X4(r0, r1, r2, r3, addr) \
    asm volatile("ldmatrix.sync.aligned.m8n8.x4.shared.b16 {%0,%1,%2,%3}, [%4];" \
                 : "=r"(r0), "=r"(r1), "=r"(r2), "=r"(r3) : "r"(addr))

#define MMA16816(d, a, b) \
    asm volatile("mma.sync.aligned.m16n8k16.row.col.f32.bf16.bf16.f32 " \
                 "{%0,%1,%2,%3}, {%4,%5,%6,%7}, {%8,%9}, {%0,%1,%2,%3};" \
                 : "+f"((d)[0]), "+f"((d)[1]), "+f"((d)[2]), "+f"((d)[3]) \
                 : "r"((a)[0]), "r"((a)[1]), "r"((a)[2]), "r"((a)[3]), \
                   "r"((b)[0]), "r"((b)[1]))

// ------------------------- pack kernels ------------------------------------
__global__ void pack_x(const float* __restrict__ x) {
    int i = blockIdx.x * blockDim.x + threadIdx.x;
    if (i >= N_TOK * HR) return;
    int n = i / HR, k = i - n * HR;
    float v = 2.0f * x[(size_t)n * H + k * 4];      // sqrt(R)=2 exactly
    g_xred[i] = v;
    g_abf[i] = __float2bfloat16(v);
}
__global__ void pack_e(const float* __restrict__ e) {
    int i = blockIdx.x * blockDim.x + threadIdx.x;
    if (i >= VP * HR) return;
    int v = i / HR, k = i - v * HR;
    float val = (v < VOC) ? 2.0f * e[(size_t)v * H + k * 4] : 0.0f;
    g_ered[i] = val;
    g_bbf[i] = __float2bfloat16(val);
}

// ------------------------- 16-warp pipelined bf16 GEMM + fused epilogue ----
// CTA tile 128(M) x 256(N), K=192 in 3 chunks of 64 (128B rows), 2 stages.
// 512 threads / 16 warps; warp tile 64x32 (2 M-groups x 8 N-groups).
#define STAGE_A  (128 * 128)            // 16384 B
#define STAGE_B  (256 * 128)            // 32768 B
#define STAGE_SZ (STAGE_A + STAGE_B)    // 49152 B
#define GEMM_SMEM (2 * STAGE_SZ)        // 98304 B

__global__ __launch_bounds__(512, 1) void gemm_mma() {
    extern __shared__ __align__(1024) char smem[];
    const uint32_t sb = smem_u32(smem);
    const int tid = threadIdx.x;
    const int bm = blockIdx.y * 128;
    const int bn = blockIdx.x * 256;

    const char* gA = (const char*)g_abf + (size_t)bm * 384;
    const char* gB = (const char*)g_bbf + (size_t)bn * 384;

    auto load_chunk = [&](int kc, int stage) {
#pragma unroll
        for (int it = 0; it < 6; it++) {
            int s = tid + it * 512;              // 0..3071 16B transfers
            if (s < 1024) {                       // A: 128 rows x 8 chunks
                int r = s >> 3, c = s & 7;
                CP_ASYNC16(sb + stage * STAGE_SZ + r * 128 + ((c ^ (r & 7)) << 4),
                           gA + (size_t)r * 384 + kc * 128 + c * 16);
            } else {                              // B: 256 rows x 8 chunks
                int t = s - 1024; int r = t >> 3, c = t & 7;
                CP_ASYNC16(sb + stage * STAGE_SZ + STAGE_A + r * 128 +
                               ((c ^ (r & 7)) << 4),
                           gB + (size_t)r * 384 + kc * 128 + c * 16);
            }
        }
        CP_COMMIT();
    };

    const int w = tid >> 5, lane = tid & 31;
    const int wm = (w >> 3) * 64;        // 2 M-warp-groups
    const int wn = (w & 7) * 32;         // 8 N-warp-groups
    const int arow0 = wm + (lane & 15);
    const int aco   = (lane >> 4);
    const int brow0 = wn + (lane & 7) + ((lane >> 4) << 3);
    const int bco   = (lane >> 3) & 1;

    float acc[4][4][4];
#pragma unroll
    for (int mi = 0; mi < 4; mi++)
#pragma unroll
        for (int ni = 0; ni < 4; ni++)
#pragma unroll
            for (int q = 0; q < 4; q++) acc[mi][ni][q] = 0.0f;

    auto compute_stage = [&](int stage) {        // arg is a STAGE index (0/1)
        const uint32_t sA = sb + stage * STAGE_SZ;
        const uint32_t sB = sA + STAGE_A;
#pragma unroll
        for (int k16 = 0; k16 < 4; k16++) {
            uint32_t a[4][4];
#pragma unroll
            for (int mi = 0; mi < 4; mi++) {
                int r = arow0 + mi * 16;
                int c = (k16 * 2 + aco) ^ (r & 7);
                LDSM_X4(a[mi][0], a[mi][1], a[mi][2], a[mi][3],
                        sA + r * 128 + (c << 4));
            }
            uint32_t b[4][2];
#pragma unroll
            for (int p = 0; p < 2; p++) {
                int r = brow0 + p * 16;
                int c = (k16 * 2 + bco) ^ (r & 7);
                uint32_t r0, r1, r2, r3;
                LDSM_X4(r0, r1, r2, r3, sB + r * 128 + (c << 4));
                b[2 * p + 0][0] = r0; b[2 * p + 0][1] = r1;
                b[2 * p + 1][0] = r2; b[2 * p + 1][1] = r3;
            }
#pragma unroll
            for (int mi = 0; mi < 4; mi++)
#pragma unroll
                for (int ni = 0; ni < 4; ni++)
                    MMA16816(acc[mi][ni], a[mi], b[ni]);
        }
    };

    // ---- pipeline: chunks 0,1,2 -> stages 0,1,0
    load_chunk(0, 0);
    load_chunk(1, 1);
    CP_WAITG(1); __syncthreads();        // chunk 0 (stage 0) ready
    compute_stage(0);
    __syncthreads();                      // stage 0 free for chunk 2
    load_chunk(2, 0);
    CP_WAITG(1); __syncthreads();        // chunk 1 (stage 1) ready
    compute_stage(1);
    CP_WAITG(0); __syncthreads();        // chunk 2 (stage 0) ready
    compute_stage(0);

    // ---- fused epilogue: per-row Σl, Σl², top-2 per 128-col chunk
    __syncthreads();
    Part* parts = (Part*)smem;           // [128 rows][8 n-warps] = 24 KB

#pragma unroll
    for (int mi = 0; mi < 4; mi++) {
#pragma unroll
        for (int h = 0; h < 2; h++) {
            float s1 = 0.0f, s2 = 0.0f;
            float v1 = NEG_INF, v2 = NEG_INF; int i1 = 0, i2 = 0;
#pragma unroll
            for (int ni = 0; ni < 4; ni++) {
#pragma unroll
                for (int j = 0; j < 2; j++) {
                    float v = acc[mi][ni][h * 2 + j];
                    int col = wn + ni * 8 + (lane & 3) * 2 + j;
                    s1 += v; s2 = fmaf(v, v, s2);
                    if (v > v1)      { v2 = v1; i2 = i1; v1 = v; i1 = col; }
                    else if (v > v2) { v2 = v;  i2 = col; }
                }
            }
#pragma unroll
            for (int d = 1; d <= 2; d <<= 1) {
                float o1 = __shfl_xor_sync(0xffffffffu, s1, d);
                float o2 = __shfl_xor_sync(0xffffffffu, s2, d);
                float w1 = __shfl_xor_sync(0xffffffffu, v1, d);
                float w2 = __shfl_xor_sync(0xffffffffu, v2, d);
                int   j1 = __shfl_xor_sync(0xffffffffu, i1, d);
                int   j2 = __shfl_xor_sync(0xffffffffu, i2, d);
                s1 += o1; s2 += o2;
                if (w1 > v1) {
                    float nv2; int ni2;
                    if (v1 >= w2) { nv2 = v1; ni2 = i1; }
                    else          { nv2 = w2; ni2 = j2; }
                    v1 = w1; i1 = j1; v2 = nv2; i2 = ni2;
                } else if (w1 > v2) {
                    v2 = w1; i2 = j1;
                }
            }
            if ((lane & 3) == 0) {
                int r = wm + mi * 16 + h * 8 + (lane >> 2);
                Part p; p.s1 = s1; p.s2 = s2; p.v1 = v1; p.v2 = v2;
                p.i1 = i1; p.i2 = i2;
                parts[r * 8 + (w & 7)] = p;
            }
        }
    }
    __syncthreads();

    // 256 of 512 threads: (row, chunk) pairs; chunk ch merges n-warps 4ch..4ch+3
    if (tid < 256) {
        int r = tid >> 1, ch = tid & 1;
        float s1 = 0.0f, s2 = 0.0f;
        float v1 = NEG_INF, v2 = NEG_INF; int i1 = 0, i2 = 0;
#pragma unroll
        for (int q = 0; q < 4; q++) {
            Part p = parts[r * 8 + ch * 4 + q];
            s1 += p.s1; s2 += p.s2;
            if (p.v1 > v1) {
                float nv2; int ni2;
                if (v1 >= p.v2) { nv2 = v1;   ni2 = i1; }
                else            { nv2 = p.v2; ni2 = p.i2; }
                v1 = p.v1; i1 = p.i1; v2 = nv2; i2 = ni2;
            } else if (p.v1 > v2) {
                v2 = p.v1; i2 = p.i1;
            }
        }
        size_t o = (size_t)(bm + r) * NCN + blockIdx.x * 2 + ch;
        g_s12[o] = make_float2(s1, s2);
        g_cv[o]  = make_float2(v1, v2);
        g_ci[o]  = make_int2(bn + i1, bn + i2);
    }
}

// ------------------------- warp-per-row reduce: Σexp poly + top-24 ---------
// 788 candidates/row -> 25 per lane; 24 barrier-free argmax rounds.
__global__ __launch_bounds__(256) void reduce_rows() {
    const int row  = blockIdx.x * 8 + (threadIdx.x >> 5);
    const int lane = threadIdx.x & 31;

    // ---- moments: Σexp ≈ VOC + Σl + ½Σl² (pad cols are exactly 0)
    float s = 0.0f;
    for (int c = lane; c < NCN; c += 32) {
        float2 p = g_s12[(size_t)row * NCN + c];
        s += fmaf(0.5f, p.y, p.x);
    }
#pragma unroll
    for (int d = 16; d > 0; d >>= 1) s += __shfl_xor_sync(0xffffffffu, s, d);
    if (lane == 0) g_sumexp[row] = (float)VOC + s;

    // ---- candidates: 2 per chunk = 788, padded to 800 = 25 slots/lane
    float v[25]; int ix[25];
#pragma unroll
    for (int q = 0; q < 25; q++) {
        int slot = q * 32 + lane;
        int c = slot >> 1;
        if (c < NCN) {
            float2 cv = g_cv[(size_t)row * NCN + c];
            int2   ci = g_ci[(size_t)row * NCN + c];
            v[q]  = (slot & 1) ? cv.y : cv.x;
            ix[q] = (slot & 1) ? ci.y : ci.x;
        } else { v[q] = NEG_INF; ix[q] = 0x7fffffff; }
    }

    for (int r = 0; r < TOPC; r++) {
        float bv = v[0]; int bi = ix[0];
#pragma unroll
        for (int q = 1; q < 25; q++)
            if (v[q] > bv || (v[q] == bv && ix[q] < bi)) { bv = v[q]; bi = ix[q]; }
#pragma unroll
        for (int d = 16; d > 0; d >>= 1) {
            float ov = __shfl_xor_sync(0xffffffffu, bv, d);
            int   oi = __shfl_xor_sync(0xffffffffu, bi, d);
            if (ov > bv || (ov == bv && oi < bi)) { bv = ov; bi = oi; }
        }
        if (lane == 0) g_candi[row * TOPC + r] = bi;
#pragma unroll
        for (int q = 0; q < 25; q++)             // consume winner (idx unique)
            if (v[q] == bv && ix[q] == bi) v[q] = NEG_INF;
    }
}

// ------------------------- fp32 refine: exact reduced logits, top-10 -------
__global__ __launch_bounds__(256) void refine() {
    const int row = blockIdx.x;
    const int tid = threadIdx.x;
    const int w = tid >> 5, lane = tid & 31;
    __shared__ float xs[HR];
    __shared__ float cval[TOPC];
    __shared__ int   cidx[TOPC];

    for (int i = tid; i < HR; i += 256) xs[i] = g_xred[(size_t)row * HR + i];
    __syncthreads();

    for (int c = w; c < TOPC; c += 8) {
        int idx = g_candi[row * TOPC + c];
        if ((unsigned)idx >= (unsigned)VP) idx = 0;          // defensive clamp
        const float* er = g_ered + (size_t)idx * HR;
        float d = 0.0f;
#pragma unroll
        for (int h0 = 0; h0 < HR; h0 += 32) d = fmaf(xs[h0 + lane], er[h0 + lane], d);
#pragma unroll
        for (int st = 16; st > 0; st >>= 1) d += __shfl_xor_sync(0xffffffffu, d, st);
        if (lane == 0) { cval[c] = d; cidx[c] = idx; }
    }
    __syncthreads();

    if (tid == 0) {
        bool used[TOPC];
#pragma unroll
        for (int c = 0; c < TOPC; c++) used[c] = false;
#pragma unroll
        for (int r = 0; r < KTOP; r++) {
            float bv = NEG_INF; int bi = 0x7fffffff; int bp = 0;
#pragma unroll
            for (int c = 0; c < TOPC; c++) {
                if (used[c]) continue;
                if (cval[c] > bv || (cval[c] == bv && cidx[c] < bi)) {
                    bv = cval[c]; bi = cidx[c]; bp = c;
                }
            }
            used[bp] = true;
            g_topv[row * KTOP + r] = bv;
            g_topi[row * KTOP + r] = bi;
        }
    }
}

// ------------------------- exact full-H rescore + combine ------------------
__global__ __launch_bounds__(320) void rescore(const float* __restrict__ x,
                                               const float* __restrict__ emb,
                                               float* __restrict__ out) {
    const int row = blockIdx.x;
    const int tid = threadIdx.x;
    const int w = tid >> 5, lane = tid & 31;
    __shared__ float s_el[KTOP];

    if (w < KTOP) {
        int idx = g_topi[row * KTOP + w];
        if ((unsigned)idx >= (unsigned)VOC) idx = 0;         // defensive clamp
        const float* xr = x + (size_t)row * H;
        const float* er = emb + (size_t)idx * H;
        float d = 0.0f;
        for (int h = lane; h < H; h += 32) d = fmaf(xr[h], er[h], d);
#pragma unroll
        for (int st = 16; st > 0; st >>= 1) d += __shfl_xor_sync(0xffffffffu, d, st);
        if (lane == 0) s_el[w] = d;
    }
    __syncthreads();

    if (tid == 0) {
        float Z = g_sumexp[row];
        float es[KTOP]; float zs = 0.0f;
#pragma unroll
        for (int k = 0; k < KTOP; k++) { es[k] = __expf(s_el[k]); zs += es[k]; }
        float best = NEG_INF;
#pragma unroll
        for (int k = 0; k < KTOP; k++) {
            float sc = 0.5f * (es[k] / zs + __expf(g_topv[row * KTOP + k]) / Z);
            best = fmaxf(best, sc);
        }
        out[row] = best;
    }
}

// ------------------------- launch ------------------------------------------
extern "C" void kernel_launch(void* const* d_in, const int* in_sizes, int n_in,
                              void* d_out, int out_size) {
    const float* x   = (const float*)d_in[0];
    const float* emb = (const float*)d_in[1];
    if (n_in >= 2 && in_sizes[0] != N_TOK * H) {
        const float* t = x; x = emb; emb = t;
    }
    float* out = (float*)d_out;

    static bool attr_done = false;
    if (!attr_done) {
        cudaFuncSetAttribute(gemm_mma, cudaFuncAttributeMaxDynamicSharedMemorySize,
                             GEMM_SMEM);
        attr_done = true;
    }

    pack_x<<<(N_TOK * HR + 255) / 256, 256>>>(x);
    pack_e<<<(VP * HR + 255) / 256, 256>>>(emb);

    dim3 ggrid(VP / 256, N_TOK / 128);      // (197, 32)
    gemm_mma<<<ggrid, 512, GEMM_SMEM>>>();

    reduce_rows<<<N_TOK / 8, 256>>>();
    refine<<<N_TOK, 256>>>();
    rescore<<<N_TOK, 320>>>(x, emb, out);
}